// round 5
// baseline (speedup 1.0000x reference)
#include <cuda_runtime.h>
#include <math.h>
#include <stdint.h>

#define N_TOK   4096
#define D_MODEL 512
#define N_HEAD  8
#define HEAD_DIM 64
#define D_FF    1024

// ---------------- scratch (static device globals; no allocation allowed) ----
__device__ float g_Q   [N_TOK * D_MODEL];
__device__ float g_K   [N_TOK * D_MODEL];
__device__ float g_V   [N_TOK * D_MODEL];
__device__ float g_attn[N_TOK * D_MODEL];
__device__ float g_tmp [N_TOK * D_MODEL];
__device__ float g_x1  [N_TOK * D_MODEL];
__device__ float g_ff1 [N_TOK * D_FF];

// ---------------------------------------------------------------------------
// Generic tiled fp32 GEMM: C[M,N] = A[M,K] @ B[K,N] + bias (+ residual) (ReLU)
// BM=BN=64, BK=16, 256 threads, 4x4 per thread.
// Requires M%64==0, N%64==0, K%16==0 (true for all calls here).
// ---------------------------------------------------------------------------
template<bool RELU, bool RES>
__global__ void gemm_kernel(const float* __restrict__ A, const float* __restrict__ B,
                            const float* __restrict__ bias, const float* __restrict__ res,
                            float* __restrict__ C, int M, int N, int K)
{
    const int BM = 64, BN = 64, BK = 16;
    __shared__ float As[BK][BM + 4];   // stored transposed: As[k][m], stride 68 (16B aligned)
    __shared__ float Bs[BK][BN + 4];   // natural: Bs[k][n]

    const int bx = blockIdx.x;     // N tile
    const int by = blockIdx.y;     // M tile
    const int tid = threadIdx.x;   // 0..255
    const int tx = tid & 15;       // 0..15  -> 4 output cols each
    const int ty = tid >> 4;       // 0..15  -> 4 output rows each

    // A-tile loader: 64x16 floats, one float4 per thread
    const int a_row = tid >> 2;          // 0..63
    const int a_col = (tid & 3) << 2;    // 0,4,8,12
    // B-tile loader: 16x64 floats, one float4 per thread
    const int b_row = tid >> 4;          // 0..15
    const int b_col = (tid & 15) << 2;   // 0..60

    const float* Ab = A + (size_t)(by * BM) * K;
    const float* Bb = B + (size_t)(bx * BN);

    float acc[4][4];
#pragma unroll
    for (int i = 0; i < 4; i++)
#pragma unroll
        for (int j = 0; j < 4; j++) acc[i][j] = 0.f;

    for (int k0 = 0; k0 < K; k0 += BK) {
        float4 av = *(const float4*)(Ab + (size_t)a_row * K + k0 + a_col);
        As[a_col + 0][a_row] = av.x;
        As[a_col + 1][a_row] = av.y;
        As[a_col + 2][a_row] = av.z;
        As[a_col + 3][a_row] = av.w;
        float4 bv = *(const float4*)(Bb + (size_t)(k0 + b_row) * N + b_col);
        *(float4*)&Bs[b_row][b_col] = bv;
        __syncthreads();

#pragma unroll
        for (int k = 0; k < BK; k++) {
            float4 a4 = *(const float4*)&As[k][ty << 2];
            float4 b4 = *(const float4*)&Bs[k][tx << 2];
            float af[4] = {a4.x, a4.y, a4.z, a4.w};
            float bf[4] = {b4.x, b4.y, b4.z, b4.w};
#pragma unroll
            for (int i = 0; i < 4; i++)
#pragma unroll
                for (int j = 0; j < 4; j++)
                    acc[i][j] = fmaf(af[i], bf[j], acc[i][j]);
        }
        __syncthreads();
    }

    const int crow = by * BM + (ty << 2);
    const int ccol = bx * BN + (tx << 2);
    float4 bi = *(const float4*)(bias + ccol);
#pragma unroll
    for (int i = 0; i < 4; i++) {
        float4 v;
        v.x = acc[i][0] + bi.x;
        v.y = acc[i][1] + bi.y;
        v.z = acc[i][2] + bi.z;
        v.w = acc[i][3] + bi.w;
        if (RES) {
            float4 r = *(const float4*)(res + (size_t)(crow + i) * N + ccol);
            v.x += r.x; v.y += r.y; v.z += r.z; v.w += r.w;
        }
        if (RELU) {
            v.x = fmaxf(v.x, 0.f); v.y = fmaxf(v.y, 0.f);
            v.z = fmaxf(v.z, 0.f); v.w = fmaxf(v.w, 0.f);
        }
        *(float4*)(C + (size_t)(crow + i) * N + ccol) = v;
    }
}

// ---------------------------------------------------------------------------
// Flash-style attention. CTA = 64 queries x 1 head. 256 threads (16x16),
// 4x4 fragment per thread. Online softmax; bias streamed from gmem once.
// Q,K,V: [N_TOK, D_MODEL] with head h at columns h*64 .. h*64+63.
// ---------------------------------------------------------------------------
#define ATT_STRIDE 68   // 64 + 4 pad, keeps float4 alignment

__global__ void attn_kernel(const float* __restrict__ Q, const float* __restrict__ K,
                            const float* __restrict__ V, const float* __restrict__ bias,
                            float* __restrict__ O)
{
    extern __shared__ float sm[];
    float (*Qs)[ATT_STRIDE] = (float (*)[ATT_STRIDE])(sm);                   // Q^T: Qs[d][q]
    float (*Ks)[ATT_STRIDE] = (float (*)[ATT_STRIDE])(sm + 64 * ATT_STRIDE); // K^T: Ks[d][kv]
    float (*Vs)[ATT_STRIDE] = (float (*)[ATT_STRIDE])(sm + 2 * 64 * ATT_STRIDE); // V: Vs[kv][dv]
    float (*Ps)[ATT_STRIDE] = (float (*)[ATT_STRIDE])(sm + 3 * 64 * ATT_STRIDE); // P^T: Ps[kv][q]

    const int h  = blockIdx.y;
    const int q0 = blockIdx.x * 64;
    const int tid = threadIdx.x;
    const int tx = tid & 15;
    const int ty = tid >> 4;

    // load Q tile transposed (once)
    for (int idx = tid; idx < 64 * 16; idx += 256) {
        int r  = idx >> 4;
        int c4 = (idx & 15) << 2;
        float4 t = *(const float4*)(Q + (size_t)(q0 + r) * D_MODEL + h * HEAD_DIM + c4);
        Qs[c4 + 0][r] = t.x;
        Qs[c4 + 1][r] = t.y;
        Qs[c4 + 2][r] = t.z;
        Qs[c4 + 3][r] = t.w;
    }

    float o[4][4];
    float m[4], l[4];
#pragma unroll
    for (int i = 0; i < 4; i++) {
        m[i] = -INFINITY; l[i] = 0.f;
#pragma unroll
        for (int j = 0; j < 4; j++) o[i][j] = 0.f;
    }

    const float* bbase = bias + ((size_t)h * N_TOK + q0) * N_TOK;

    for (int j0 = 0; j0 < N_TOK; j0 += 64) {
        __syncthreads();   // previous iteration finished reading Vs/Ps

        // load K tile transposed, V tile natural
        for (int idx = tid; idx < 64 * 16; idx += 256) {
            int r  = idx >> 4;
            int c4 = (idx & 15) << 2;
            float4 t = *(const float4*)(K + (size_t)(j0 + r) * D_MODEL + h * HEAD_DIM + c4);
            Ks[c4 + 0][r] = t.x;
            Ks[c4 + 1][r] = t.y;
            Ks[c4 + 2][r] = t.z;
            Ks[c4 + 3][r] = t.w;
            float4 v = *(const float4*)(V + (size_t)(j0 + r) * D_MODEL + h * HEAD_DIM + c4);
            *(float4*)&Vs[r][c4] = v;
        }
        __syncthreads();

        // S = Q K^T (fragment), rows q = 4*ty+i, cols kv = 4*tx+j
        float s[4][4];
#pragma unroll
        for (int i = 0; i < 4; i++)
#pragma unroll
            for (int j = 0; j < 4; j++) s[i][j] = 0.f;
#pragma unroll 8
        for (int k = 0; k < 64; k++) {
            float4 a4 = *(const float4*)&Qs[k][ty << 2];
            float4 b4 = *(const float4*)&Ks[k][tx << 2];
            float af[4] = {a4.x, a4.y, a4.z, a4.w};
            float bf[4] = {b4.x, b4.y, b4.z, b4.w};
#pragma unroll
            for (int i = 0; i < 4; i++)
#pragma unroll
                for (int j = 0; j < 4; j++)
                    s[i][j] = fmaf(af[i], bf[j], s[i][j]);
        }

        // scale + bias (coalesced float4 stream; each bias element read exactly once)
#pragma unroll
        for (int i = 0; i < 4; i++) {
            float4 b4 = *(const float4*)(bbase + (size_t)((ty << 2) + i) * N_TOK + j0 + (tx << 2));
            s[i][0] = fmaf(s[i][0], 0.125f, b4.x);
            s[i][1] = fmaf(s[i][1], 0.125f, b4.y);
            s[i][2] = fmaf(s[i][2], 0.125f, b4.z);
            s[i][3] = fmaf(s[i][3], 0.125f, b4.w);
        }

        // online softmax (row reduce across the 16 tx lanes)
#pragma unroll
        for (int i = 0; i < 4; i++) {
            float mloc = fmaxf(fmaxf(s[i][0], s[i][1]), fmaxf(s[i][2], s[i][3]));
#pragma unroll
            for (int off = 1; off < 16; off <<= 1)
                mloc = fmaxf(mloc, __shfl_xor_sync(0xffffffffu, mloc, off));
            float mnew  = fmaxf(m[i], mloc);
            float alpha = __expf(m[i] - mnew);
            float rsum = 0.f;
#pragma unroll
            for (int j = 0; j < 4; j++) {
                float p = __expf(s[i][j] - mnew);
                Ps[(tx << 2) + j][(ty << 2) + i] = p;
                rsum += p;
            }
#pragma unroll
            for (int off = 1; off < 16; off <<= 1)
                rsum += __shfl_xor_sync(0xffffffffu, rsum, off);
            l[i] = l[i] * alpha + rsum;
            m[i] = mnew;
#pragma unroll
            for (int j = 0; j < 4; j++) o[i][j] *= alpha;
        }
        __syncthreads();

        // O += P V  (rows q = 4*ty+i, cols dv = 4*tx+j)
#pragma unroll 8
        for (int kv = 0; kv < 64; kv++) {
            float4 p4 = *(const float4*)&Ps[kv][ty << 2];
            float4 v4 = *(const float4*)&Vs[kv][tx << 2];
            float pf[4] = {p4.x, p4.y, p4.z, p4.w};
            float vf[4] = {v4.x, v4.y, v4.z, v4.w};
#pragma unroll
            for (int i = 0; i < 4; i++)
#pragma unroll
                for (int j = 0; j < 4; j++)
                    o[i][j] = fmaf(pf[i], vf[j], o[i][j]);
        }
    }

    // normalize + store
#pragma unroll
    for (int i = 0; i < 4; i++) {
        float inv = 1.f / l[i];
        float4 v;
        v.x = o[i][0] * inv;
        v.y = o[i][1] * inv;
        v.z = o[i][2] * inv;
        v.w = o[i][3] * inv;
        *(float4*)(O + (size_t)(q0 + (ty << 2) + i) * D_MODEL + h * HEAD_DIM + (tx << 2)) = v;
    }
}

// ---------------------------------------------------------------------------
// LayerNorm over last dim (512). One warp per row, 16 floats per lane.
// ---------------------------------------------------------------------------
__global__ void layernorm_kernel(const float* __restrict__ in, const float* __restrict__ gamma,
                                 const float* __restrict__ beta, float* __restrict__ out)
{
    const int row  = blockIdx.x * 8 + (threadIdx.x >> 5);
    const int lane = threadIdx.x & 31;
    const float* r = in + (size_t)row * D_MODEL;

    float v[16];
    float sum = 0.f;
#pragma unroll
    for (int w = 0; w < 4; w++) {
        float4 t = *(const float4*)(r + w * 128 + lane * 4);
        v[w * 4 + 0] = t.x; v[w * 4 + 1] = t.y; v[w * 4 + 2] = t.z; v[w * 4 + 3] = t.w;
        sum += t.x + t.y + t.z + t.w;
    }
#pragma unroll
    for (int off = 16; off; off >>= 1) sum += __shfl_xor_sync(0xffffffffu, sum, off);
    float mu = sum * (1.f / 512.f);

    float vs = 0.f;
#pragma unroll
    for (int q = 0; q < 16; q++) {
        float d = v[q] - mu;
        vs += d * d;
    }
#pragma unroll
    for (int off = 16; off; off >>= 1) vs += __shfl_xor_sync(0xffffffffu, vs, off);
    float rstd = rsqrtf(vs * (1.f / 512.f) + 1e-5f);

#pragma unroll
    for (int w = 0; w < 4; w++) {
        int c = w * 128 + lane * 4;
        float4 g4 = *(const float4*)(gamma + c);
        float4 b4 = *(const float4*)(beta + c);
        float4 ov;
        ov.x = (v[w * 4 + 0] - mu) * rstd * g4.x + b4.x;
        ov.y = (v[w * 4 + 1] - mu) * rstd * g4.y + b4.y;
        ov.z = (v[w * 4 + 2] - mu) * rstd * g4.z + b4.z;
        ov.w = (v[w * 4 + 3] - mu) * rstd * g4.w + b4.w;
        *(float4*)(out + (size_t)row * D_MODEL + c) = ov;
    }
}

// ---------------------------------------------------------------------------
extern "C" void kernel_launch(void* const* d_in, const int* in_sizes, int n_in,
                              void* d_out, int out_size)
{
    (void)in_sizes; (void)n_in; (void)out_size;
    const float* x  = (const float*)d_in[0];
    const float* ab = (const float*)d_in[1];
    const float* Wq = (const float*)d_in[2];
    const float* bq = (const float*)d_in[3];
    const float* Wk = (const float*)d_in[4];
    const float* bk = (const float*)d_in[5];
    const float* Wv = (const float*)d_in[6];
    const float* bv = (const float*)d_in[7];
    const float* Wo = (const float*)d_in[8];
    const float* bo = (const float*)d_in[9];
    const float* g1 = (const float*)d_in[10];
    const float* b1 = (const float*)d_in[11];
    const float* g2 = (const float*)d_in[12];
    const float* b2 = (const float*)d_in[13];
    const float* W1 = (const float*)d_in[14];
    const float* c1 = (const float*)d_in[15];
    const float* W2 = (const float*)d_in[16];
    const float* c2 = (const float*)d_in[17];
    float* out = (float*)d_out;

    float *Qp, *Kp, *Vp, *ATp, *TMPp, *X1p, *FFp;
    cudaGetSymbolAddress((void**)&Qp,  g_Q);
    cudaGetSymbolAddress((void**)&Kp,  g_K);
    cudaGetSymbolAddress((void**)&Vp,  g_V);
    cudaGetSymbolAddress((void**)&ATp, g_attn);
    cudaGetSymbolAddress((void**)&TMPp,g_tmp);
    cudaGetSymbolAddress((void**)&X1p, g_x1);
    cudaGetSymbolAddress((void**)&FFp, g_ff1);

    const dim3 blk(256);
    const dim3 gg_d(D_MODEL / 64, N_TOK / 64);   // (Ntiles, Mtiles) for N=512
    const dim3 gg_f(D_FF   / 64, N_TOK / 64);    // for N=1024

    // QKV projections
    gemm_kernel<false, false><<<gg_d, blk>>>(x, Wq, bq, nullptr, Qp, N_TOK, D_MODEL, D_MODEL);
    gemm_kernel<false, false><<<gg_d, blk>>>(x, Wk, bk, nullptr, Kp, N_TOK, D_MODEL, D_MODEL);
    gemm_kernel<false, false><<<gg_d, blk>>>(x, Wv, bv, nullptr, Vp, N_TOK, D_MODEL, D_MODEL);

    // flash attention (bias streamed once)
    const int smem_att = 4 * 64 * ATT_STRIDE * (int)sizeof(float);   // 69632 B
    cudaFuncSetAttribute(attn_kernel, cudaFuncAttributeMaxDynamicSharedMemorySize, smem_att);
    attn_kernel<<<dim3(N_TOK / 64, N_HEAD), blk, smem_att>>>(Qp, Kp, Vp, ab, ATp);

    // output projection + residual, LN1
    gemm_kernel<false, true><<<gg_d, blk>>>(ATp, Wo, bo, x, TMPp, N_TOK, D_MODEL, D_MODEL);
    layernorm_kernel<<<N_TOK / 8, blk>>>(TMPp, g1, b1, X1p);

    // FFN
    gemm_kernel<true,  false><<<gg_f, blk>>>(X1p, W1, c1, nullptr, FFp, N_TOK, D_FF, D_MODEL);
    gemm_kernel<false, true ><<<gg_d, blk>>>(FFp, W2, c2, X1p, TMPp, N_TOK, D_MODEL, D_FF);
    layernorm_kernel<<<N_TOK / 8, blk>>>(TMPp, g2, b2, out);
}

// round 7
// speedup vs baseline: 1.0037x; 1.0037x over previous
#include <cuda_runtime.h>
#include <math.h>
#include <stdint.h>

#define N_TOK   4096
#define D_MODEL 512
#define N_HEAD  8
#define HEAD_DIM 64
#define D_FF    1024

// ---------------- scratch (static device globals; no allocation allowed) ----
__device__ float g_Q   [N_TOK * D_MODEL];
__device__ float g_K   [N_TOK * D_MODEL];
__device__ float g_V   [N_TOK * D_MODEL];
__device__ float g_attn[N_TOK * D_MODEL];
__device__ float g_tmp [N_TOK * D_MODEL];
__device__ float g_x1  [N_TOK * D_MODEL];
__device__ float g_ff1 [N_TOK * D_FF];

// ---------------------------------------------------------------------------
// Generic tiled fp32 GEMM: C[M,N] = A[M,K] @ B[K,N] + bias (+ residual) (ReLU)
// BM=BN=64, BK=16, 256 threads, 4x4 per thread.
// Requires M%64==0, N%64==0, K%16==0 (true for all calls here).
// ---------------------------------------------------------------------------
template<bool RELU, bool RES>
__global__ void gemm_kernel(const float* __restrict__ A, const float* __restrict__ B,
                            const float* __restrict__ bias, const float* __restrict__ res,
                            float* __restrict__ C, int M, int N, int K)
{
    const int BM = 64, BN = 64, BK = 16;
    __shared__ float As[BK][BM + 4];   // stored transposed: As[k][m], stride 68 (16B aligned)
    __shared__ float Bs[BK][BN + 4];   // natural: Bs[k][n]

    const int bx = blockIdx.x;     // N tile
    const int by = blockIdx.y;     // M tile
    const int tid = threadIdx.x;   // 0..255
    const int tx = tid & 15;       // 0..15  -> 4 output cols each
    const int ty = tid >> 4;       // 0..15  -> 4 output rows each

    // A-tile loader: 64x16 floats, one float4 per thread
    const int a_row = tid >> 2;          // 0..63
    const int a_col = (tid & 3) << 2;    // 0,4,8,12
    // B-tile loader: 16x64 floats, one float4 per thread
    const int b_row = tid >> 4;          // 0..15
    const int b_col = (tid & 15) << 2;   // 0..60

    const float* Ab = A + (size_t)(by * BM) * K;
    const float* Bb = B + (size_t)(bx * BN);

    float acc[4][4];
#pragma unroll
    for (int i = 0; i < 4; i++)
#pragma unroll
        for (int j = 0; j < 4; j++) acc[i][j] = 0.f;

    for (int k0 = 0; k0 < K; k0 += BK) {
        float4 av = *(const float4*)(Ab + (size_t)a_row * K + k0 + a_col);
        As[a_col + 0][a_row] = av.x;
        As[a_col + 1][a_row] = av.y;
        As[a_col + 2][a_row] = av.z;
        As[a_col + 3][a_row] = av.w;
        float4 bv = *(const float4*)(Bb + (size_t)(k0 + b_row) * N + b_col);
        *(float4*)&Bs[b_row][b_col] = bv;
        __syncthreads();

#pragma unroll
        for (int k = 0; k < BK; k++) {
            float4 a4 = *(const float4*)&As[k][ty << 2];
            float4 b4 = *(const float4*)&Bs[k][tx << 2];
            float af[4] = {a4.x, a4.y, a4.z, a4.w};
            float bf[4] = {b4.x, b4.y, b4.z, b4.w};
#pragma unroll
            for (int i = 0; i < 4; i++)
#pragma unroll
                for (int j = 0; j < 4; j++)
                    acc[i][j] = fmaf(af[i], bf[j], acc[i][j]);
        }
        __syncthreads();
    }

    const int crow = by * BM + (ty << 2);
    const int ccol = bx * BN + (tx << 2);
    float4 bi = *(const float4*)(bias + ccol);
#pragma unroll
    for (int i = 0; i < 4; i++) {
        float4 v;
        v.x = acc[i][0] + bi.x;
        v.y = acc[i][1] + bi.y;
        v.z = acc[i][2] + bi.z;
        v.w = acc[i][3] + bi.w;
        if (RES) {
            float4 r = *(const float4*)(res + (size_t)(crow + i) * N + ccol);
            v.x += r.x; v.y += r.y; v.z += r.z; v.w += r.w;
        }
        if (RELU) {
            v.x = fmaxf(v.x, 0.f); v.y = fmaxf(v.y, 0.f);
            v.z = fmaxf(v.z, 0.f); v.w = fmaxf(v.w, 0.f);
        }
        *(float4*)(C + (size_t)(crow + i) * N + ccol) = v;
    }
}

// ---------------------------------------------------------------------------
// Flash-style attention. CTA = 64 queries x 1 head. 256 threads (16x16),
// 4x4 fragment per thread. Online softmax; bias streamed from gmem once.
// Q,K,V: [N_TOK, D_MODEL] with head h at columns h*64 .. h*64+63.
// ---------------------------------------------------------------------------
#define ATT_STRIDE 68   // 64 + 4 pad, keeps float4 alignment

__global__ void attn_kernel(const float* __restrict__ Q, const float* __restrict__ K,
                            const float* __restrict__ V, const float* __restrict__ bias,
                            float* __restrict__ O)
{
    extern __shared__ float sm[];
    float (*Qs)[ATT_STRIDE] = (float (*)[ATT_STRIDE])(sm);                   // Q^T: Qs[d][q]
    float (*Ks)[ATT_STRIDE] = (float (*)[ATT_STRIDE])(sm + 64 * ATT_STRIDE); // K^T: Ks[d][kv]
    float (*Vs)[ATT_STRIDE] = (float (*)[ATT_STRIDE])(sm + 2 * 64 * ATT_STRIDE); // V: Vs[kv][dv]
    float (*Ps)[ATT_STRIDE] = (float (*)[ATT_STRIDE])(sm + 3 * 64 * ATT_STRIDE); // P^T: Ps[kv][q]

    const int h  = blockIdx.y;
    const int q0 = blockIdx.x * 64;
    const int tid = threadIdx.x;
    const int tx = tid & 15;
    const int ty = tid >> 4;

    // load Q tile transposed (once)
    for (int idx = tid; idx < 64 * 16; idx += 256) {
        int r  = idx >> 4;
        int c4 = (idx & 15) << 2;
        float4 t = *(const float4*)(Q + (size_t)(q0 + r) * D_MODEL + h * HEAD_DIM + c4);
        Qs[c4 + 0][r] = t.x;
        Qs[c4 + 1][r] = t.y;
        Qs[c4 + 2][r] = t.z;
        Qs[c4 + 3][r] = t.w;
    }

    float o[4][4];
    float m[4], l[4];
#pragma unroll
    for (int i = 0; i < 4; i++) {
        m[i] = -INFINITY; l[i] = 0.f;
#pragma unroll
        for (int j = 0; j < 4; j++) o[i][j] = 0.f;
    }

    const float* bbase = bias + ((size_t)h * N_TOK + q0) * N_TOK;

    for (int j0 = 0; j0 < N_TOK; j0 += 64) {
        __syncthreads();   // previous iteration finished reading Vs/Ps

        // load K tile transposed, V tile natural
        for (int idx = tid; idx < 64 * 16; idx += 256) {
            int r  = idx >> 4;
            int c4 = (idx & 15) << 2;
            float4 t = *(const float4*)(K + (size_t)(j0 + r) * D_MODEL + h * HEAD_DIM + c4);
            Ks[c4 + 0][r] = t.x;
            Ks[c4 + 1][r] = t.y;
            Ks[c4 + 2][r] = t.z;
            Ks[c4 + 3][r] = t.w;
            float4 v = *(const float4*)(V + (size_t)(j0 + r) * D_MODEL + h * HEAD_DIM + c4);
            *(float4*)&Vs[r][c4] = v;
        }
        __syncthreads();

        // S = Q K^T (fragment), rows q = 4*ty+i, cols kv = 4*tx+j
        float s[4][4];
#pragma unroll
        for (int i = 0; i < 4; i++)
#pragma unroll
            for (int j = 0; j < 4; j++) s[i][j] = 0.f;
#pragma unroll 8
        for (int k = 0; k < 64; k++) {
            float4 a4 = *(const float4*)&Qs[k][ty << 2];
            float4 b4 = *(const float4*)&Ks[k][tx << 2];
            float af[4] = {a4.x, a4.y, a4.z, a4.w};
            float bf[4] = {b4.x, b4.y, b4.z, b4.w};
#pragma unroll
            for (int i = 0; i < 4; i++)
#pragma unroll
                for (int j = 0; j < 4; j++)
                    s[i][j] = fmaf(af[i], bf[j], s[i][j]);
        }

        // scale + bias (coalesced float4 stream; each bias element read exactly once)
#pragma unroll
        for (int i = 0; i < 4; i++) {
            float4 b4 = *(const float4*)(bbase + (size_t)((ty << 2) + i) * N_TOK + j0 + (tx << 2));
            s[i][0] = fmaf(s[i][0], 0.125f, b4.x);
            s[i][1] = fmaf(s[i][1], 0.125f, b4.y);
            s[i][2] = fmaf(s[i][2], 0.125f, b4.z);
            s[i][3] = fmaf(s[i][3], 0.125f, b4.w);
        }

        // online softmax (row reduce across the 16 tx lanes)
#pragma unroll
        for (int i = 0; i < 4; i++) {
            float mloc = fmaxf(fmaxf(s[i][0], s[i][1]), fmaxf(s[i][2], s[i][3]));
#pragma unroll
            for (int off = 1; off < 16; off <<= 1)
                mloc = fmaxf(mloc, __shfl_xor_sync(0xffffffffu, mloc, off));
            float mnew  = fmaxf(m[i], mloc);
            float alpha = __expf(m[i] - mnew);
            float rsum = 0.f;
#pragma unroll
            for (int j = 0; j < 4; j++) {
                float p = __expf(s[i][j] - mnew);
                Ps[(tx << 2) + j][(ty << 2) + i] = p;
                rsum += p;
            }
#pragma unroll
            for (int off = 1; off < 16; off <<= 1)
                rsum += __shfl_xor_sync(0xffffffffu, rsum, off);
            l[i] = l[i] * alpha + rsum;
            m[i] = mnew;
#pragma unroll
            for (int j = 0; j < 4; j++) o[i][j] *= alpha;
        }
        __syncthreads();

        // O += P V  (rows q = 4*ty+i, cols dv = 4*tx+j)
#pragma unroll 8
        for (int kv = 0; kv < 64; kv++) {
            float4 p4 = *(const float4*)&Ps[kv][ty << 2];
            float4 v4 = *(const float4*)&Vs[kv][tx << 2];
            float pf[4] = {p4.x, p4.y, p4.z, p4.w};
            float vf[4] = {v4.x, v4.y, v4.z, v4.w};
#pragma unroll
            for (int i = 0; i < 4; i++)
#pragma unroll
                for (int j = 0; j < 4; j++)
                    o[i][j] = fmaf(pf[i], vf[j], o[i][j]);
        }
    }

    // normalize + store
#pragma unroll
    for (int i = 0; i < 4; i++) {
        float inv = 1.f / l[i];
        float4 v;
        v.x = o[i][0] * inv;
        v.y = o[i][1] * inv;
        v.z = o[i][2] * inv;
        v.w = o[i][3] * inv;
        *(float4*)(O + (size_t)(q0 + (ty << 2) + i) * D_MODEL + h * HEAD_DIM + (tx << 2)) = v;
    }
}

// ---------------------------------------------------------------------------
// LayerNorm over last dim (512). One warp per row, 16 floats per lane.
// ---------------------------------------------------------------------------
__global__ void layernorm_kernel(const float* __restrict__ in, const float* __restrict__ gamma,
                                 const float* __restrict__ beta, float* __restrict__ out)
{
    const int row  = blockIdx.x * 8 + (threadIdx.x >> 5);
    const int lane = threadIdx.x & 31;
    const float* r = in + (size_t)row * D_MODEL;

    float v[16];
    float sum = 0.f;
#pragma unroll
    for (int w = 0; w < 4; w++) {
        float4 t = *(const float4*)(r + w * 128 + lane * 4);
        v[w * 4 + 0] = t.x; v[w * 4 + 1] = t.y; v[w * 4 + 2] = t.z; v[w * 4 + 3] = t.w;
        sum += t.x + t.y + t.z + t.w;
    }
#pragma unroll
    for (int off = 16; off; off >>= 1) sum += __shfl_xor_sync(0xffffffffu, sum, off);
    float mu = sum * (1.f / 512.f);

    float vs = 0.f;
#pragma unroll
    for (int q = 0; q < 16; q++) {
        float d = v[q] - mu;
        vs += d * d;
    }
#pragma unroll
    for (int off = 16; off; off >>= 1) vs += __shfl_xor_sync(0xffffffffu, vs, off);
    float rstd = rsqrtf(vs * (1.f / 512.f) + 1e-5f);

#pragma unroll
    for (int w = 0; w < 4; w++) {
        int c = w * 128 + lane * 4;
        float4 g4 = *(const float4*)(gamma + c);
        float4 b4 = *(const float4*)(beta + c);
        float4 ov;
        ov.x = (v[w * 4 + 0] - mu) * rstd * g4.x + b4.x;
        ov.y = (v[w * 4 + 1] - mu) * rstd * g4.y + b4.y;
        ov.z = (v[w * 4 + 2] - mu) * rstd * g4.z + b4.z;
        ov.w = (v[w * 4 + 3] - mu) * rstd * g4.w + b4.w;
        *(float4*)(out + (size_t)row * D_MODEL + c) = ov;
    }
}

// ---------------------------------------------------------------------------
extern "C" void kernel_launch(void* const* d_in, const int* in_sizes, int n_in,
                              void* d_out, int out_size)
{
    (void)in_sizes; (void)n_in; (void)out_size;
    const float* x  = (const float*)d_in[0];
    const float* ab = (const float*)d_in[1];
    const float* Wq = (const float*)d_in[2];
    const float* bq = (const float*)d_in[3];
    const float* Wk = (const float*)d_in[4];
    const float* bk = (const float*)d_in[5];
    const float* Wv = (const float*)d_in[6];
    const float* bv = (const float*)d_in[7];
    const float* Wo = (const float*)d_in[8];
    const float* bo = (const float*)d_in[9];
    const float* g1 = (const float*)d_in[10];
    const float* b1 = (const float*)d_in[11];
    const float* g2 = (const float*)d_in[12];
    const float* b2 = (const float*)d_in[13];
    const float* W1 = (const float*)d_in[14];
    const float* c1 = (const float*)d_in[15];
    const float* W2 = (const float*)d_in[16];
    const float* c2 = (const float*)d_in[17];
    float* out = (float*)d_out;

    float *Qp, *Kp, *Vp, *ATp, *TMPp, *X1p, *FFp;
    cudaGetSymbolAddress((void**)&Qp,  g_Q);
    cudaGetSymbolAddress((void**)&Kp,  g_K);
    cudaGetSymbolAddress((void**)&Vp,  g_V);
    cudaGetSymbolAddress((void**)&ATp, g_attn);
    cudaGetSymbolAddress((void**)&TMPp,g_tmp);
    cudaGetSymbolAddress((void**)&X1p, g_x1);
    cudaGetSymbolAddress((void**)&FFp, g_ff1);

    const dim3 blk(256);
    const dim3 gg_d(D_MODEL / 64, N_TOK / 64);   // (Ntiles, Mtiles) for N=512
    const dim3 gg_f(D_FF   / 64, N_TOK / 64);    // for N=1024

    // QKV projections
    gemm_kernel<false, false><<<gg_d, blk>>>(x, Wq, bq, nullptr, Qp, N_TOK, D_MODEL, D_MODEL);
    gemm_kernel<false, false><<<gg_d, blk>>>(x, Wk, bk, nullptr, Kp, N_TOK, D_MODEL, D_MODEL);
    gemm_kernel<false, false><<<gg_d, blk>>>(x, Wv, bv, nullptr, Vp, N_TOK, D_MODEL, D_MODEL);

    // flash attention (bias streamed once)
    const int smem_att = 4 * 64 * ATT_STRIDE * (int)sizeof(float);   // 69632 B
    cudaFuncSetAttribute(attn_kernel, cudaFuncAttributeMaxDynamicSharedMemorySize, smem_att);
    attn_kernel<<<dim3(N_TOK / 64, N_HEAD), blk, smem_att>>>(Qp, Kp, Vp, ab, ATp);

    // output projection + residual, LN1
    gemm_kernel<false, true><<<gg_d, blk>>>(ATp, Wo, bo, x, TMPp, N_TOK, D_MODEL, D_MODEL);
    layernorm_kernel<<<N_TOK / 8, blk>>>(TMPp, g1, b1, X1p);

    // FFN
    gemm_kernel<true,  false><<<gg_f, blk>>>(X1p, W1, c1, nullptr, FFp, N_TOK, D_FF, D_MODEL);
    gemm_kernel<false, true ><<<gg_d, blk>>>(FFp, W2, c2, X1p, TMPp, N_TOK, D_MODEL, D_FF);
    layernorm_kernel<<<N_TOK / 8, blk>>>(TMPp, g2, b2, out);
}